// round 17
// baseline (speedup 1.0000x reference)
#include <cuda_runtime.h>
#include <cuda_fp16.h>
#include <cstdint>

#define D    128
#define BM   128
#define NMAX 100000
#define LDH  136   // padded row stride in halves (272B: conflict-free ldmatrix)

// fp16 node features for the edge gather (51MB working set fits L2).
__device__ __half g_hp [(size_t)NMAX * D];
__device__ __half g_hpH[(size_t)NMAX * D];
// Combined B matrix, n-major: rows [0,128) = W[j][k]; rows [128,256) = M2[k][n]^T
// i.e. g_B[128+n][d] = M2[d][n] where M2 = W^T @ H.
__device__ __half g_B[256 * D];
// Combined bias: [0,128) = Wb ; [128,256) = c2 = b @ H.  (fp32)
__device__ float g_bias2[256];

__device__ __forceinline__ uint32_t h2u(__half2 v) {
    return *reinterpret_cast<uint32_t*>(&v);
}
__device__ __forceinline__ __half2 u2h(uint32_t v) {
    return *reinterpret_cast<__half2*>(&v);
}

__device__ __forceinline__ void mma16816h(uint32_t& c0, uint32_t& c1,
                                          uint32_t a0, uint32_t a1,
                                          uint32_t a2, uint32_t a3,
                                          uint32_t b0, uint32_t b1) {
    asm volatile(
        "mma.sync.aligned.m16n8k16.row.col.f16.f16.f16.f16 "
        "{%0,%1}, {%2,%3,%4,%5}, {%6,%7}, {%0,%1};"
        : "+r"(c0), "+r"(c1)
        : "r"(a0), "r"(a1), "r"(a2), "r"(a3), "r"(b0), "r"(b1));
}
__device__ __forceinline__ void ldm_x4(uint32_t& r0, uint32_t& r1,
                                       uint32_t& r2, uint32_t& r3,
                                       const __half* p) {
    uint32_t a = (uint32_t)__cvta_generic_to_shared(p);
    asm volatile("ldmatrix.sync.aligned.m8n8.x4.shared.b16 {%0,%1,%2,%3}, [%4];"
                 : "=r"(r0), "=r"(r1), "=r"(r2), "=r"(r3) : "r"(a));
}

// ============================================================================
// Prep: M2 = W^T @ H (fp32), c2 = b @ H; pack g_B = [W | M2^T-rows], g_bias2.
// 128 blocks x 128 threads; block j handles H column j.
// ============================================================================
__global__ __launch_bounds__(128)
void prep_kernel(const float* __restrict__ Ww,
                 const float* __restrict__ Wb,
                 const float* __restrict__ Hm)
{
    const int j = blockIdx.x;   // 0..127
    const int t = threadIdx.x;  // 0..127

    // g_B[j][k] = W[j][k]  (coalesced over k = t)
    g_B[j * D + t] = __float2half_rn(Ww[j * D + t]);

    // M2[d][j] = sum_k W[k][d] * H[k][j]   (d = t; W read coalesced over d,
    // H read broadcast). Write g_B[(128+j)][d] = M2[d][j]  (coalesced over d).
    float acc = 0.f;
    #pragma unroll 8
    for (int k = 0; k < D; ++k)
        acc = fmaf(Ww[k * D + t], Hm[k * D + j], acc);
    g_B[(128 + j) * D + t] = __float2half_rn(acc);

    if (t == 0) {
        float c2 = 0.f;
        #pragma unroll 8
        for (int k = 0; k < D; ++k)
            c2 = fmaf(Wb[k], Hm[k * D + j], c2);
        g_bias2[128 + j] = c2;
        g_bias2[j] = Wb[j];
    }
}

// ============================================================================
// Node transform, single GEMM: [hp | hpH] = h @ g_B^T + g_bias2.
// 512 threads = 16 warps as 4(m) x 4(n); warp tile = 32 rows x 64 cols.
// fp16 HMMA, fp16 accumulate. One staging, one GEMM phase, one epilogue.
// ============================================================================
__global__ __launch_bounds__(512, 1)
void node_kernel(const float* __restrict__ h, int N)
{
    extern __shared__ char smem[];
    __half2* biash = reinterpret_cast<__half2*>(smem);        // 128 half2 = 512 B
    __half*  As    = reinterpret_cast<__half*>(smem + 512);   // h tile [128][LDH]
    __half*  Bs    = As + 128 * LDH;                          // B [256][LDH]; reused as
                                                              // output stage [128][2*LDH]
    const int tid  = threadIdx.x;
    const int row0 = blockIdx.x * BM;

    if (tid < 128) {
        const float2 b2 = reinterpret_cast<const float2*>(g_bias2)[tid];
        biash[tid] = __floats2half2_rn(b2.x, b2.y);
    }

    // ---- stage h tile: row r = tid>>2, 32 cols each ----
    {
        const int r = tid >> 2;
        const int q = tid & 3;
        int grow = row0 + r; if (grow >= N) grow = N - 1;
        const float4* hr = reinterpret_cast<const float4*>(h + (size_t)grow * D);
        #pragma unroll
        for (int u = 0; u < 8; ++u) {
            float4 v = hr[q * 8 + u];
            uint2 p;
            p.x = h2u(__floats2half2_rn(v.x, v.y));
            p.y = h2u(__floats2half2_rn(v.z, v.w));
            *reinterpret_cast<uint2*>(&As[r * LDH + (q * 32 + u * 4)]) = p;
        }
    }
    // ---- stage B (fp16, straight copy): row n = tid>>1, 64 cols each ----
    {
        const int n = tid >> 1;
        const int q = tid & 1;
        const uint4* srcp = reinterpret_cast<const uint4*>(g_B + n * D + q * 64);
        uint4* dstp = reinterpret_cast<uint4*>(&Bs[n * LDH + q * 64]);
        #pragma unroll
        for (int u = 0; u < 8; ++u) dstp[u] = srcp[u];
    }
    __syncthreads();

    const int warp = tid >> 5;
    const int lane = tid & 31;
    const int m0   = (warp >> 2) * 32;       // warp row base (0,32,64,96)
    const int n0   = (warp & 3) * 64;        // warp col base (0,64,128,192)
    const int qr   = lane >> 2;
    const int qc   = (lane & 3) * 2;

    const int aRow = (lane & 15);
    const int aCol = (lane >> 4) * 8;
    const int bRow = ((lane >> 4) << 3) + (lane & 7);    // n-major B
    const int bCol = ((lane >> 3) & 1) * 8;

    // f16 accumulators: 2(m) x 8(n) x 2 regs
    uint32_t acc[2][8][2];
    #pragma unroll
    for (int mt = 0; mt < 2; ++mt)
        #pragma unroll
        for (int nt = 0; nt < 8; ++nt)
            acc[mt][nt][0] = acc[mt][nt][1] = 0u;

    // ================= single GEMM: [hp|hpH] = h @ B^T =================
    #pragma unroll
    for (int ks = 0; ks < 8; ++ks) {
        const int kb = ks * 16;
        uint32_t A[2][4], B[4][4];
        #pragma unroll
        for (int mt = 0; mt < 2; ++mt)
            ldm_x4(A[mt][0], A[mt][1], A[mt][2], A[mt][3],
                   &As[(m0 + mt * 16 + aRow) * LDH + kb + aCol]);
        #pragma unroll
        for (int np = 0; np < 4; ++np)
            ldm_x4(B[np][0], B[np][1], B[np][2], B[np][3],
                   &Bs[(n0 + np * 16 + bRow) * LDH + kb + bCol]);
        #pragma unroll
        for (int mt = 0; mt < 2; ++mt)
            #pragma unroll
            for (int nt = 0; nt < 8; ++nt)
                mma16816h(acc[mt][nt][0], acc[mt][nt][1],
                          A[mt][0], A[mt][1], A[mt][2], A[mt][3],
                          B[nt >> 1][(nt & 1) * 2], B[nt >> 1][(nt & 1) * 2 + 1]);
    }

    __syncthreads();   // all reads of As/Bs complete

    // ---- epilogue: +bias, scatter into stage = Bs viewed as [128][2*LDH] ----
    __half* stage = Bs;
    #pragma unroll
    for (int mt = 0; mt < 2; ++mt) {
        const int r = m0 + mt * 16 + qr;
        #pragma unroll
        for (int nt = 0; nt < 8; ++nt) {
            const int c = n0 + nt * 8 + qc;     // 0..255
            const __half2 b2 = biash[c >> 1];
            *reinterpret_cast<uint32_t*>(&stage[r * (2 * LDH) + c]) =
                h2u(__hadd2(u2h(acc[mt][nt][0]), b2));
            *reinterpret_cast<uint32_t*>(&stage[(r + 8) * (2 * LDH) + c]) =
                h2u(__hadd2(u2h(acc[mt][nt][1]), b2));
        }
    }
    __syncthreads();

    // ---- coalesced stores: thread r=tid>>2 handles 64-col segment q ----
    {
        const int r = tid >> 2;
        const int q = tid & 3;
        const int grow = row0 + r;
        if (grow < N) {
            const uint4* srcp = reinterpret_cast<const uint4*>(&stage[r * (2 * LDH) + q * 64]);
            __half* gbase = (q < 2) ? (g_hp  + (size_t)grow * D + q * 64)
                                    : (g_hpH + (size_t)grow * D + (q - 2) * 64);
            uint4* dstp = reinterpret_cast<uint4*>(gbase);
            #pragma unroll
            for (int u = 0; u < 8; ++u) dstp[u] = srcp[u];
        }
    }
}

// ============================================================================
// Edge kernel: 2 edges per 16-lane group, 4 independent LDG.128 per thread.
// (unchanged from R15/R16)
// ============================================================================
__global__ __launch_bounds__(256)
void edge_kernel(const int* __restrict__ src,
                 const int* __restrict__ dst,
                 float* __restrict__ out, int E, int N)
{
    int grp  = (int)((blockIdx.x * blockDim.x + threadIdx.x) >> 4);
    int slot = threadIdx.x & 15;
    int e0   = grp * 2;
    if (e0 >= E) return;
    int e1 = e0 + 1;
    bool has1 = (e1 < E);

    int s0 = __ldg(src + e0);
    int d0 = __ldg(dst + e0);
    int s1 = has1 ? __ldg(src + e1) : s0;
    int d1 = has1 ? __ldg(dst + e1) : d0;
    s0 = min(max(s0, 0), N - 1);  d0 = min(max(d0, 0), N - 1);
    s1 = min(max(s1, 0), N - 1);  d1 = min(max(d1, 0), N - 1);

    uint4 a0 = reinterpret_cast<const uint4*>(g_hp  + (size_t)s0 * D)[slot];
    uint4 b0 = reinterpret_cast<const uint4*>(g_hpH + (size_t)d0 * D)[slot];
    uint4 a1 = reinterpret_cast<const uint4*>(g_hp  + (size_t)s1 * D)[slot];
    uint4 b1 = reinterpret_cast<const uint4*>(g_hpH + (size_t)d1 * D)[slot];

    float sum0 = 0.f, sum1 = 0.f;
    {
        const __half2* ah = reinterpret_cast<const __half2*>(&a0);
        const __half2* bh = reinterpret_cast<const __half2*>(&b0);
        #pragma unroll
        for (int i = 0; i < 4; ++i) {
            float2 fa = __half22float2(ah[i]);
            float2 fb = __half22float2(bh[i]);
            float dx = fa.x - fb.x, dy = fa.y - fb.y;
            sum0 = fmaf(dx, dx, sum0);
            sum0 = fmaf(dy, dy, sum0);
        }
    }
    {
        const __half2* ah = reinterpret_cast<const __half2*>(&a1);
        const __half2* bh = reinterpret_cast<const __half2*>(&b1);
        #pragma unroll
        for (int i = 0; i < 4; ++i) {
            float2 fa = __half22float2(ah[i]);
            float2 fb = __half22float2(bh[i]);
            float dx = fa.x - fb.x, dy = fa.y - fb.y;
            sum1 = fmaf(dx, dx, sum1);
            sum1 = fmaf(dy, dy, sum1);
        }
    }
    #pragma unroll
    for (int off = 8; off; off >>= 1) {
        sum0 += __shfl_xor_sync(0xffffffffu, sum0, off);
        sum1 += __shfl_xor_sync(0xffffffffu, sum1, off);
    }

    if (slot == 0) {
        out[e0] = sum0;
        if (has1) out[e1] = sum1;
    }
}

extern "C" void kernel_launch(void* const* d_in, const int* in_sizes, int n_in,
                              void* d_out, int out_size)
{
    const float* h   = (const float*)d_in[0];
    const int*   src = (const int*)d_in[1];
    const int*   dst = (const int*)d_in[2];
    const float* Ww  = (const float*)d_in[3];
    const float* Wb  = (const float*)d_in[4];
    const float* Hm  = (const float*)d_in[5];
    float*       out = (float*)d_out;

    int N = in_sizes[0] / D;
    if (N > NMAX) N = NMAX;
    int E = in_sizes[1];

    prep_kernel<<<128, 128>>>(Ww, Wb, Hm);

    const int smem_bytes = 512 + 3 * 128 * LDH * (int)sizeof(__half); // 104960 B
    cudaFuncSetAttribute(node_kernel,
                         cudaFuncAttributeMaxDynamicSharedMemorySize, smem_bytes);

    int nblocks = (N + BM - 1) / BM;
    node_kernel<<<nblocks, 512, smem_bytes>>>(h, N);

    int eblocks = ((E + 1) / 2 + 15) / 16;
    edge_kernel<<<eblocks, 256>>>(src, dst, out, E, N);
}